// round 7
// baseline (speedup 1.0000x reference)
#include <cuda_runtime.h>
#include <cuda_bf16.h>
#include <cstdint>

#define BB 8
#define CC 64
#define NN 4096
#define KK 20
#define OO 64
#define SLOPE 0.01f
#define NEG_INF __int_as_float(0xff800000)

// ---------------- scratch ----------------
__device__ float         g_xx [BB * NN];
__device__ __nv_bfloat16 g_xhi[BB * NN * CC];   // [b][n][c], 128B rows
__device__ __nv_bfloat16 g_xlo[BB * NN * CC];
__device__ float         g_y1 [BB * NN * OO];
__device__ float         g_c  [BB * NN * OO];
__device__ int           g_idx[BB * NN * KK];

// ---------------- helpers ----------------
__device__ __forceinline__ uint32_t smem_u32(const void* p) {
    uint32_t a;
    asm("{ .reg .u64 t; cvta.to.shared.u64 t, %1; cvt.u32.u64 %0, t; }"
        : "=r"(a) : "l"(p));
    return a;
}
__device__ __forceinline__ uint32_t sw128(uint32_t off) {
    return off ^ ((off >> 3) & 0x70);
}
__device__ __forceinline__ void ldsm4(uint32_t (&r)[4], uint32_t addr) {
    asm volatile("ldmatrix.sync.aligned.m8n8.x4.shared.b16 {%0,%1,%2,%3}, [%4];"
                 : "=r"(r[0]), "=r"(r[1]), "=r"(r[2]), "=r"(r[3]) : "r"(addr));
}
__device__ __forceinline__ void mma16816(float (&d)[4], const uint32_t (&a)[4],
                                         uint32_t b0, uint32_t b1) {
    asm volatile(
        "mma.sync.aligned.m16n8k16.row.col.f32.bf16.bf16.f32 "
        "{%0,%1,%2,%3}, {%4,%5,%6,%7}, {%8,%9}, {%0,%1,%2,%3};"
        : "+f"(d[0]), "+f"(d[1]), "+f"(d[2]), "+f"(d[3])
        : "r"(a[0]), "r"(a[1]), "r"(a[2]), "r"(a[3]), "r"(b0), "r"(b1));
}
#define CPASYNC16(dst, src) \
    asm volatile("cp.async.cg.shared.global [%0], [%1], 16;" \
                 :: "r"(dst), "l"(src) : "memory")
#define CP_COMMIT() asm volatile("cp.async.commit_group;" ::: "memory")
#define CP_WAIT1()  asm volatile("cp.async.wait_group 1;" ::: "memory")

// ---------------------------------------------------------------------------
// Kernel 1: fused xx + bf16 hi/lo split, transposed to [b][n][c]
// ---------------------------------------------------------------------------
__global__ void k_pre(const float* __restrict__ x) {
    int t = blockIdx.x * 256 + threadIdx.x;      // b*NN + n
    int b = t >> 12;
    const float* xp = x + (size_t)b * CC * NN + (t & (NN - 1));
    float s = 0.f;
    uint32_t hw[CC / 2], lw[CC / 2];
#pragma unroll
    for (int c2 = 0; c2 < CC / 2; ++c2) {
        float v0 = xp[(size_t)(2 * c2) * NN];
        float v1 = xp[(size_t)(2 * c2 + 1) * NN];
        s = fmaf(v0, v0, s);
        s = fmaf(v1, v1, s);
        __nv_bfloat16 h0 = __float2bfloat16(v0);
        __nv_bfloat16 h1 = __float2bfloat16(v1);
        __nv_bfloat16 l0 = __float2bfloat16(v0 - __bfloat162float(h0));
        __nv_bfloat16 l1 = __float2bfloat16(v1 - __bfloat162float(h1));
        hw[c2] = (uint32_t)__bfloat16_as_ushort(h0) |
                 ((uint32_t)__bfloat16_as_ushort(h1) << 16);
        lw[c2] = (uint32_t)__bfloat16_as_ushort(l0) |
                 ((uint32_t)__bfloat16_as_ushort(l1) << 16);
    }
    g_xx[t] = s;
    uint4* ph = (uint4*)(g_xhi + (size_t)t * CC);
    uint4* pl = (uint4*)(g_xlo + (size_t)t * CC);
#pragma unroll
    for (int q = 0; q < 8; ++q) {
        ph[q] = make_uint4(hw[4*q], hw[4*q+1], hw[4*q+2], hw[4*q+3]);
        pl[q] = make_uint4(lw[4*q], lw[4*q+1], lw[4*q+2], lw[4*q+3]);
    }
}

// ---------------------------------------------------------------------------
// Kernel 2: projections y1 = W1 @ x, c = (W2 - W1) @ x
// ---------------------------------------------------------------------------
__global__ void k_proj(const float* __restrict__ x, const float* __restrict__ W) {
    __shared__ float Ws[OO * 2 * CC];
    int tid = threadIdx.x;
    for (int i = tid; i < OO * 2 * CC; i += blockDim.x) Ws[i] = W[i];
    __syncthreads();

    int t = blockIdx.x * blockDim.x + tid;
    int b = t >> 12;
    const float* xp = x + (size_t)b * CC * NN + (t & (NN - 1));
    float xc[CC];
#pragma unroll
    for (int c = 0; c < CC; ++c) xc[c] = xp[(size_t)c * NN];

    float* y1p = g_y1 + (size_t)t * OO;
    float* cp  = g_c  + (size_t)t * OO;
#pragma unroll 4
    for (int o = 0; o < OO; ++o) {
        const float* wr = Ws + o * 2 * CC;
        float a1 = 0.f, a2 = 0.f;
#pragma unroll
        for (int c = 0; c < CC; ++c) {
            a1 = fmaf(wr[c],      xc[c], a1);
            a2 = fmaf(wr[CC + c], xc[c], a2);
        }
        y1p[o] = a1;
        cp[o]  = a2 - a1;
    }
}

// ---------------------------------------------------------------------------
// Kernel 3: mma.sync kNN, cp.async double-buffered, interleaved mma issue.
// Grid 256 = 8 batches x 32 i-blocks, 256 threads, 2 CTAs/SM.
// ---------------------------------------------------------------------------
#define SM_AHI 0
#define SM_ALO 16384
#define SM_B   32768                       // 2 stages x (8KB hi + 8KB lo)
#define SM_XXD 65536                       // 2 stages x 256B
#define SM_SCR 66048                       // 8 warps x 16 x 66 floats = 33792
#define SM_CB  99840                       // 8 warps x 32 lanes x 8 = 8192
#define SMEM_TOTAL 108032
#define SCR_STRIDE 66

__device__ __forceinline__ void tk_insert(float (&tv)[KK], int (&ti)[KK],
                                          float& vmin, int& minpos, float s, int j) {
#pragma unroll
    for (int k = 0; k < KK; ++k)
        if (k == minpos) { tv[k] = s; ti[k] = j; }
    float vm = tv[0]; int mp = 0;
#pragma unroll
    for (int k = 1; k < KK; ++k)
        if (tv[k] < vm) { vm = tv[k]; mp = k; }
    vmin = vm; minpos = mp;
}

__global__ void __launch_bounds__(256, 2) k_knn_mma() {
    extern __shared__ char smem[];
    uint32_t sb = smem_u32(smem);
    int tid = threadIdx.x;
    int w   = tid >> 5;
    int l   = tid & 31;
    int b   = blockIdx.x >> 5;
    int ib  = blockIdx.x & 31;

    // ---- stage A tiles (128 rows x 64 bf16, hi+lo), sw128 swizzled ----
    {
        const uint4* Ah = (const uint4*)(g_xhi + ((size_t)b * NN + ib * 128) * CC);
        const uint4* Al = (const uint4*)(g_xlo + ((size_t)b * NN + ib * 128) * CC);
        for (int q = tid; q < 1024; q += 256) {
            uint32_t sw = sw128((uint32_t)q * 16);
            *(uint4*)(smem + SM_AHI + sw) = Ah[q];
            *(uint4*)(smem + SM_ALO + sw) = Al[q];
        }
    }

    float* scr  = (float*)(smem + SM_SCR) + w * (16 * SCR_STRIDE);
    int*   cbuf = (int*)(smem + SM_CB) + w * (32 * 8);   // FIX: 256-int warp stride

    // ldmatrix lane roles
    uint32_t aRow = (uint32_t)(w * 16 + (l & 15));
    uint32_t aChunkBase = (uint32_t)(l >> 4);
    uint32_t bRowL  = (uint32_t)((l & 7) + ((l >> 4) & 1) * 8);
    uint32_t bChunk = (uint32_t)((l >> 3) & 1);

    int   srow    = l >> 1;
    int   colbase = (l & 1) * 32;
    const float* srowp = scr + srow * SCR_STRIDE;

    // ---- cp.async stage fill ----
    auto fill_stage = [&](int s, int jt) {
        const char* Bh = (const char*)(g_xhi + ((size_t)b * NN + jt * 64) * CC);
        const char* Bl = (const char*)(g_xlo + ((size_t)b * NN + jt * 64) * CC);
        uint32_t base = sb + SM_B + s * 16384;
#pragma unroll
        for (int r = 0; r < 2; ++r) {
            int q = tid + r * 256;
            uint32_t sw = sw128((uint32_t)q * 16);
            CPASYNC16(base + sw,        Bh + q * 16);
            CPASYNC16(base + 8192 + sw, Bl + q * 16);
        }
        if (tid < 16)
            CPASYNC16(sb + SM_XXD + s * 256 + tid * 16,
                      (const char*)(g_xx + b * NN + jt * 64) + tid * 16);
    };

    fill_stage(0, 0);
    CP_COMMIT();

    float tv[KK]; int ti[KK];
    float vmin = NEG_INF; int minpos = 0;

    for (int t = 0; t < 64; ++t) {
        int j0 = t * 64;
        int s  = t & 1;
        if (t + 1 < 64) fill_stage(s ^ 1, t + 1);
        CP_COMMIT();
        CP_WAIT1();
        __syncthreads();

        uint32_t bHiBase = sb + SM_B + s * 16384;
        uint32_t bLoBase = bHiBase + 8192;
        const float* xxs = (const float*)(smem + SM_XXD + s * 256);

        // ---- compute 16x64 scores per warp ----
        float acc[8][4];
#pragma unroll
        for (int nt = 0; nt < 8; ++nt)
#pragma unroll
            for (int q = 0; q < 4; ++q) acc[nt][q] = 0.f;

#pragma unroll
        for (int ks = 0; ks < 4; ++ks) {
            uint32_t aOff = sw128(aRow * 128 + (ks * 2 + aChunkBase) * 16);
            uint32_t ahi[4], alo[4];
            ldsm4(ahi, sb + SM_AHI + aOff);
            ldsm4(alo, sb + SM_ALO + aOff);
            uint32_t bh[4][4], bl[4][4];
#pragma unroll
            for (int p = 0; p < 4; ++p) {
                uint32_t bOff = sw128((p * 16 + bRowL) * 128 + (ks * 2 + bChunk) * 16);
                ldsm4(bh[p], bHiBase + bOff);
                ldsm4(bl[p], bLoBase + bOff);
            }
            // interleaved issue: dependency distance 8 mma per accumulator
#pragma unroll
            for (int p = 0; p < 4; ++p) {
                mma16816(acc[2*p],     ahi, bh[p][0], bh[p][1]);
                mma16816(acc[2*p + 1], ahi, bh[p][2], bh[p][3]);
            }
#pragma unroll
            for (int p = 0; p < 4; ++p) {
                mma16816(acc[2*p],     ahi, bl[p][0], bl[p][1]);
                mma16816(acc[2*p + 1], ahi, bl[p][2], bl[p][3]);
            }
#pragma unroll
            for (int p = 0; p < 4; ++p) {
                mma16816(acc[2*p],     alo, bh[p][0], bh[p][1]);
                mma16816(acc[2*p + 1], alo, bh[p][2], bh[p][3]);
            }
        }

        // ---- scores -> smem: s = 2*dot - xx[j] ----
        {
            int r0 = (l >> 2);
            int c0 = 2 * (l & 3);
#pragma unroll
            for (int nt = 0; nt < 8; ++nt) {
                float2 xv = *(const float2*)&xxs[nt * 8 + c0];
                float2 s01, s23;
                s01.x = fmaf(2.f, acc[nt][0], -xv.x);
                s01.y = fmaf(2.f, acc[nt][1], -xv.y);
                s23.x = fmaf(2.f, acc[nt][2], -xv.x);
                s23.y = fmaf(2.f, acc[nt][3], -xv.y);
                *(float2*)&scr[r0       * SCR_STRIDE + nt * 8 + c0] = s01;
                *(float2*)&scr[(r0 + 8) * SCR_STRIDE + nt * 8 + c0] = s23;
            }
        }
        __syncwarp();

        // ---- selection: each lane scans its half-row ----
        if (t == 0) {
#pragma unroll
            for (int q = 0; q < KK; ++q) {
                tv[q] = srowp[colbase + q];
                ti[q] = j0 + colbase + q;
            }
            float vm = tv[0]; int mp = 0;
#pragma unroll
            for (int k = 1; k < KK; ++k)
                if (tv[k] < vm) { vm = tv[k]; mp = k; }
            vmin = vm; minpos = mp;
#pragma unroll
            for (int q = KK; q < 32; ++q) {
                float sc = srowp[colbase + q];
                if (sc > vmin) tk_insert(tv, ti, vmin, minpos, sc, j0 + colbase + q);
            }
        } else {
            int cnt = 0;
#pragma unroll
            for (int q = 0; q < 32; ++q) {
                float sc = srowp[colbase + q];
                if (sc > vmin) {
                    if (cnt < 8) { cbuf[cnt * 32 + l] = colbase + q; ++cnt; }
                    else tk_insert(tv, ti, vmin, minpos, sc, j0 + colbase + q);
                }
            }
            for (int u = 0; u < cnt; ++u) {
                int col = cbuf[u * 32 + l];
                float sc = srowp[col];
                if (sc > vmin) tk_insert(tv, ti, vmin, minpos, sc, j0 + col);
            }
        }
        __syncthreads();
    }

    // ---- exact merge: 2 half-row top-20s -> row top-20 ----
    {
        float* mv = (float*)smem;                 // [128*2][20] vals
        int*   mi = (int*)(smem + 20480);         // [128*2][20] idx
        int rowg = w * 16 + srow;
        int half = l & 1;
#pragma unroll
        for (int k = 0; k < KK; ++k) {
            mv[(rowg * 2 + half) * KK + k] = tv[k];
            mi[(rowg * 2 + half) * KK + k] = ti[k];
        }
        __syncthreads();
        if (tid < 128) {
            float* v  = mv + tid * 2 * KK;
            int*   id = mi + tid * 2 * KK;
            int gi = b * NN + ib * 128 + tid;
            int* op = g_idx + (size_t)gi * KK;
            for (int s = 0; s < KK; ++s) {
                float best = NEG_INF; int bslot = 0;
#pragma unroll
                for (int q = 0; q < 2 * KK; ++q) {
                    float vv = v[q];
                    if (vv > best) { best = vv; bslot = q; }
                }
                op[s] = id[bslot];
                v[bslot] = NEG_INF;
            }
        }
    }
}

// ---------------------------------------------------------------------------
// Kernel 4: gather + max + leaky
// ---------------------------------------------------------------------------
__global__ void k_out(float* __restrict__ out) {
    int o  = threadIdx.x & 63;
    int nn = threadIdx.x >> 6;
    int t  = blockIdx.x * 4 + nn;
    int b  = t >> 12;
    int n  = t & (NN - 1);

    const int* ip = g_idx + (size_t)t * KK;
    float cadd = g_c[(size_t)t * OO + o];

    float m = NEG_INF;
#pragma unroll
    for (int k = 0; k < KK; ++k) {
        int j = ip[k];
        float v = g_y1[(((size_t)b * NN) + j) * OO + o];
        m = fmaxf(m, v);
    }
    float h = m + cadd;
    out[((size_t)b * OO + o) * NN + n] = (h >= 0.f) ? h : SLOPE * h;
}

// ---------------------------------------------------------------------------
extern "C" void kernel_launch(void* const* d_in, const int* in_sizes, int n_in,
                              void* d_out, int out_size) {
    const float* x = (const float*)d_in[0];
    const float* W = (const float*)d_in[1];
    float* out = (float*)d_out;

    static bool attr_set = false;
    if (!attr_set) {
        cudaFuncSetAttribute(k_knn_mma, cudaFuncAttributeMaxDynamicSharedMemorySize,
                             SMEM_TOTAL);
        attr_set = true;
    }

    k_pre    <<<BB * NN / 256, 256>>>(x);
    k_proj   <<<BB * NN / 128, 128>>>(x, W);
    k_knn_mma<<<256, 256, SMEM_TOTAL>>>();
    k_out    <<<BB * NN / 4, 256>>>(out);
}